// round 9
// baseline (speedup 1.0000x reference)
#include <cuda_runtime.h>

// DendriticBranchLayerSparse
//   x:           [1024, 32768] f32  -> [1024, 8192] float4
//   t:           [1024]        f32
//   weight_vals: [32768]       f32  -> [8192] float4
//   t_weights:   [8192, 1]     f32
//   out:         [1024, 8192]  f32
//
// out[b,o] = dot(w4[o], x4[b,o]) + t[b]*t_weights[o]
//
// Thread <-> output column o, R=32 batch rows. Loop restructured into
// chunks of 8 rows with an explicit load phase (float4 xv[8]) so ptxas
// keeps 8 LDG.128 in flight (previous build had regs=32 => MLP_eff ~2-3,
// latency-bound at DRAM=72%). t fetched as float4 (4x fewer t loads).

static constexpr int BATCH   = 1024;
static constexpr int NUM_OUT = 8192;
static constexpr int R       = 32;   // batch rows per thread
static constexpr int C       = 8;    // rows per chunk (loads in flight)

__global__ void __launch_bounds__(256)
dendritic_kernel(const float4* __restrict__ x4,
                 const float*  __restrict__ t,
                 const float4* __restrict__ w4,
                 const float*  __restrict__ tw,
                 float* __restrict__ out)
{
    int idx = blockIdx.x * blockDim.x + threadIdx.x;
    int o  = idx & (NUM_OUT - 1);       // output column (lane-consecutive -> coalesced)
    int rg = idx >> 13;                 // row-group index
    int b0 = rg * R;

    const float4 w   = __ldg(&w4[o]);
    const float  twv = __ldg(&tw[o]);

    const float4* xrow = x4 + (size_t)b0 * NUM_OUT + o;
    float*        orow = out + (size_t)b0 * NUM_OUT + o;
    const float4* t4   = (const float4*)(t + b0);   // b0 % 32 == 0 -> aligned

    #pragma unroll
    for (int c = 0; c < R / C; c++) {
        // ---- load phase: 8 independent streaming LDG.128 + 2 t loads ----
        float4 xv[C];
        #pragma unroll
        for (int r = 0; r < C; r++)
            xv[r] = __ldcs(&xrow[(size_t)(c * C + r) * NUM_OUT]);

        float4 ta = __ldg(&t4[c * 2 + 0]);
        float4 tb = __ldg(&t4[c * 2 + 1]);
        float tv[C] = {ta.x, ta.y, ta.z, ta.w, tb.x, tb.y, tb.z, tb.w};

        // ---- compute + store phase ----
        #pragma unroll
        for (int r = 0; r < C; r++) {
            float res = fmaf(xv[r].x, w.x,
                        fmaf(xv[r].y, w.y,
                        fmaf(xv[r].z, w.z,
                        fmaf(xv[r].w, w.w, tv[r] * twv))));
            __stcs(&orow[(size_t)(c * C + r) * NUM_OUT], res);
        }
    }
}

extern "C" void kernel_launch(void* const* d_in, const int* in_sizes, int n_in,
                              void* d_out, int out_size)
{
    const float4* x4 = (const float4*)d_in[0];
    const float*  t  = (const float*) d_in[1];
    const float4* w4 = (const float4*)d_in[2];
    const float*  tw = (const float*) d_in[3];
    float* out = (float*)d_out;

    const int total_threads = NUM_OUT * (BATCH / R);  // 262144
    const int block = 256;
    const int grid  = total_threads / block;          // 1024

    dendritic_kernel<<<grid, block>>>(x4, t, w4, tw, out);
}